// round 1
// baseline (speedup 1.0000x reference)
#include <cuda_runtime.h>
#include <cstdint>

// Problem constants
#define Bb 4
#define Tt 8192
#define Hh 1024
#define Rr 1024
#define N1 2048          // 2*R
#define NSEG 64
#define SEGLEN 128       // Tt / NSEG

// ---------------- scratch (static device globals; no allocation) ----------------
__device__ float g_x1[(size_t)Bb * Tt * Hh];        // conv output  (134 MB)
__device__ float g_zh[(size_t)Bb * Tt * N1];        // GEMM1 output (268 MB)
__device__ float g_ho[(size_t)Bb * Tt * Rr];        // scan output  (134 MB)
__device__ float g_segA[(size_t)Bb * NSEG * Rr];
__device__ float g_segC[(size_t)Bb * NSEG * Rr];
__device__ float g_hin [(size_t)Bb * NSEG * Rr];

// ---------------- 1) residual causal depthwise conv ----------------
// x' = x + conv_b + sum_{i=0..3} w[i] * x[t-3+i]
__global__ __launch_bounds__(256) void conv_residual(
    const float* __restrict__ x, const float* __restrict__ w,
    const float* __restrict__ cb)
{
    int idx = blockIdx.x * blockDim.x + threadIdx.x;      // over B*T*(H/4)
    int h4 = idx & 255;                                   // H/4 = 256
    int t  = (idx >> 8) & (Tt - 1);
    int b  = idx >> (8 + 13);
    size_t base = (((size_t)b * Tt + t) * Hh) + (size_t)h4 * 4;

    float4 xc = *(const float4*)(x + base);
    float4 bc = *(const float4*)(cb + (size_t)h4 * 4);
    float4 acc;
    acc.x = xc.x + bc.x; acc.y = xc.y + bc.y;
    acc.z = xc.z + bc.z; acc.w = xc.w + bc.w;

#pragma unroll
    for (int i = 0; i < 4; i++) {
        int ts = t - 3 + i;
        if (ts >= 0) {
            float4 xi = (i == 3) ? xc
                : *(const float4*)(x + base + (long long)(i - 3) * Hh);
            float4 wi = *(const float4*)(w + (size_t)i * Hh + (size_t)h4 * 4);
            acc.x += wi.x * xi.x; acc.y += wi.y * xi.y;
            acc.z += wi.z * xi.z; acc.w += wi.w * xi.w;
        }
    }
    *(float4*)(g_x1 + base) = acc;
}

// ---------------- 2) SGEMM  C[M,N] = A[M,K] * B[N,K]^T ----------------
// 128x128 block tile, BK=8, 256 threads, 8x8 per thread, double-buffered smem.
__global__ __launch_bounds__(256) void sgemm_nt(
    const float* __restrict__ A, const float* __restrict__ Bm,
    float* __restrict__ C, int M, int N, int K)
{
    const int BM = 128, BN = 128, BK = 8;
    __shared__ float As[2][BK][BM];
    __shared__ float Bs[2][BK][BN];

    int tid = threadIdx.x;
    int bm = blockIdx.y * BM;
    int bn = blockIdx.x * BN;

    int loadRow = tid >> 1;           // 0..127
    int loadCol = (tid & 1) * 4;      // 0 or 4
    const float* Aptr = A + (size_t)(bm + loadRow) * K + loadCol;
    const float* Bptr = Bm + (size_t)(bn + loadRow) * K + loadCol;

    int ty = tid >> 4;                // 0..15
    int tx = tid & 15;                // 0..15

    float acc[8][8];
#pragma unroll
    for (int i = 0; i < 8; i++)
#pragma unroll
        for (int j = 0; j < 8; j++) acc[i][j] = 0.f;

    // prologue: tile 0
    {
        float4 av = *(const float4*)(Aptr);
        float4 bv = *(const float4*)(Bptr);
        As[0][loadCol + 0][loadRow] = av.x;
        As[0][loadCol + 1][loadRow] = av.y;
        As[0][loadCol + 2][loadRow] = av.z;
        As[0][loadCol + 3][loadRow] = av.w;
        Bs[0][loadCol + 0][loadRow] = bv.x;
        Bs[0][loadCol + 1][loadRow] = bv.y;
        Bs[0][loadCol + 2][loadRow] = bv.z;
        Bs[0][loadCol + 3][loadRow] = bv.w;
    }
    __syncthreads();

    int KT = K / BK;
    int cur = 0;
    for (int kt = 0; kt < KT; kt++) {
        float4 an, bnv;
        if (kt + 1 < KT) {
            an  = *(const float4*)(Aptr + (size_t)(kt + 1) * BK);
            bnv = *(const float4*)(Bptr + (size_t)(kt + 1) * BK);
        }
#pragma unroll
        for (int k = 0; k < BK; k++) {
            float am[8], bb[8];
            float4 a0 = *(const float4*)(&As[cur][k][ty * 8]);
            float4 a1 = *(const float4*)(&As[cur][k][ty * 8 + 4]);
            float4 b0 = *(const float4*)(&Bs[cur][k][tx * 8]);
            float4 b1 = *(const float4*)(&Bs[cur][k][tx * 8 + 4]);
            am[0]=a0.x; am[1]=a0.y; am[2]=a0.z; am[3]=a0.w;
            am[4]=a1.x; am[5]=a1.y; am[6]=a1.z; am[7]=a1.w;
            bb[0]=b0.x; bb[1]=b0.y; bb[2]=b0.z; bb[3]=b0.w;
            bb[4]=b1.x; bb[5]=b1.y; bb[6]=b1.z; bb[7]=b1.w;
#pragma unroll
            for (int i = 0; i < 8; i++)
#pragma unroll
                for (int j = 0; j < 8; j++)
                    acc[i][j] += am[i] * bb[j];
        }
        if (kt + 1 < KT) {
            int nxt = cur ^ 1;
            As[nxt][loadCol + 0][loadRow] = an.x;
            As[nxt][loadCol + 1][loadRow] = an.y;
            As[nxt][loadCol + 2][loadRow] = an.z;
            As[nxt][loadCol + 3][loadRow] = an.w;
            Bs[nxt][loadCol + 0][loadRow] = bnv.x;
            Bs[nxt][loadCol + 1][loadRow] = bnv.y;
            Bs[nxt][loadCol + 2][loadRow] = bnv.z;
            Bs[nxt][loadCol + 3][loadRow] = bnv.w;
            __syncthreads();
            cur = nxt;
        }
    }

#pragma unroll
    for (int i = 0; i < 8; i++) {
        size_t row = (size_t)(bm + ty * 8 + i) * N + bn + tx * 8;
        *(float4*)(C + row)     = make_float4(acc[i][0], acc[i][1], acc[i][2], acc[i][3]);
        *(float4*)(C + row + 4) = make_float4(acc[i][4], acc[i][5], acc[i][6], acc[i][7]);
    }
}

// ---------------- 3) scan: sigmoid + linear recurrence ----------------
__device__ __forceinline__ void gru_ab(float z, float hc, float& a, float& bb)
{
    float s = 1.f / (1.f + __expf(-z));
    a = 1.f - s;
    bb = s * hc;
}

// pass A: per-segment (A = prod a, C = local scan end value)
__global__ __launch_bounds__(128) void scan_passA()
{
    int r   = blockIdx.x * 128 + threadIdx.x;
    int seg = blockIdx.y;
    int b   = blockIdx.z;
    size_t base = (size_t)b * Tt * N1;
    float A = 1.f, Cc = 0.f;
    int t0 = seg * SEGLEN;
    for (int t = t0; t < t0 + SEGLEN; t++) {
        size_t off = base + (size_t)t * N1;
        float z  = g_zh[off + r];
        float hc = g_zh[off + Rr + r];
        float a, bb; gru_ab(z, hc, a, bb);
        A  *= a;
        Cc = a * Cc + bb;
    }
    size_t i = ((size_t)b * NSEG + seg) * Rr + r;
    g_segA[i] = A;
    g_segC[i] = Cc;
}

// pass B: sequential scan over segments; stores h entering each segment
__global__ __launch_bounds__(128) void scan_passB()
{
    int r = blockIdx.x * 128 + threadIdx.x;
    int b = blockIdx.z;
    float h = 0.f;
    for (int seg = 0; seg < NSEG; seg++) {
        size_t i = ((size_t)b * NSEG + seg) * Rr + r;
        g_hin[i] = h;
        h = g_segA[i] * h + g_segC[i];
    }
}

// pass C: recompute local scan with incoming prefix, write h_o [B,T,R]
__global__ __launch_bounds__(128) void scan_passC()
{
    int r   = blockIdx.x * 128 + threadIdx.x;
    int seg = blockIdx.y;
    int b   = blockIdx.z;
    size_t base = (size_t)b * Tt * N1;
    float h = g_hin[((size_t)b * NSEG + seg) * Rr + r];
    int t0 = seg * SEGLEN;
    for (int t = t0; t < t0 + SEGLEN; t++) {
        size_t off = base + (size_t)t * N1;
        float z  = g_zh[off + r];
        float hc = g_zh[off + Rr + r];
        float a, bb; gru_ab(z, hc, a, bb);
        h = a * h + bb;
        g_ho[((size_t)b * Tt + t) * Rr + r] = h;
    }
}

// ---------------- launch ----------------
extern "C" void kernel_launch(void* const* d_in, const int* in_sizes, int n_in,
                              void* d_out, int out_size)
{
    const float* x      = (const float*)d_in[0];
    const float* w_zh   = (const float*)d_in[1];
    const float* w_out  = (const float*)d_in[2];
    const float* conv_w = (const float*)d_in[3];
    const float* conv_b = (const float*)d_in[4];
    float* out = (float*)d_out;

    float* x1 = nullptr; float* zh = nullptr; float* ho = nullptr;
    cudaGetSymbolAddress((void**)&x1, g_x1);
    cudaGetSymbolAddress((void**)&zh, g_zh);
    cudaGetSymbolAddress((void**)&ho, g_ho);

    // 1) conv
    {
        int total4 = Bb * Tt * (Hh / 4);
        conv_residual<<<total4 / 256, 256>>>(x, conv_w, conv_b);
    }
    // 2) GEMM1: zh[BT, 2R] = x1[BT, H] * w_zh[2R, H]^T
    {
        dim3 grid(N1 / 128, (Bb * Tt) / 128);
        sgemm_nt<<<grid, 256>>>(x1, w_zh, zh, Bb * Tt, N1, Hh);
    }
    // 3) scan
    {
        dim3 gA(Rr / 128, NSEG, Bb);
        scan_passA<<<gA, 128>>>();
        dim3 gB(Rr / 128, 1, Bb);
        scan_passB<<<gB, 128>>>();
        scan_passC<<<gA, 128>>>();
    }
    // 4) GEMM2: out[BT, H] = ho[BT, R] * w_out[H, R]^T
    {
        dim3 grid(Hh / 128, (Bb * Tt) / 128);
        sgemm_nt<<<grid, 256>>>(ho, w_out, out, Bb * Tt, Hh, Rr);
    }
}

// round 3
// speedup vs baseline: 3.0414x; 3.0414x over previous
#include <cuda_runtime.h>
#include <cstdint>

// Problem constants
#define Bb 4
#define Tt 8192
#define Hh 1024
#define Rr 1024
#define N1 2048          // 2*R
#define NSEG 64
#define SEGLEN 128       // Tt / NSEG

// ---------------- scratch (static device globals; no allocation) ----------------
__device__ float g_x1[(size_t)Bb * Tt * Hh];        // conv output  (134 MB)
__device__ float g_zh[(size_t)Bb * Tt * N1];        // GEMM1 output (268 MB)
__device__ float g_ho[(size_t)Bb * Tt * Rr];        // scan output  (134 MB)
__device__ float g_segA[(size_t)Bb * NSEG * Rr];
__device__ float g_segC[(size_t)Bb * NSEG * Rr];
__device__ float g_hin [(size_t)Bb * NSEG * Rr];

// ================= helpers =================
__device__ __forceinline__ uint32_t smem_to_u32(const void* p) {
    uint32_t a;
    asm("{ .reg .u64 t; cvta.to.shared.u64 t, %1; cvt.u32.u64 %0, t; }" : "=r"(a) : "l"(p));
    return a;
}
__device__ __forceinline__ void cp_async16(uint32_t dst, const void* src) {
    asm volatile("cp.async.cg.shared.global [%0], [%1], 16;" :: "r"(dst), "l"(src) : "memory");
}
#define CP_COMMIT() asm volatile("cp.async.commit_group;" ::: "memory")
#define CP_WAIT(n)  asm volatile("cp.async.wait_group %0;" :: "n"(n) : "memory")

__device__ __forceinline__ uint32_t f2tf32(float f) {
    uint32_t r;
    asm("cvt.rna.tf32.f32 %0, %1;" : "=r"(r) : "f"(f));
    return r;
}
__device__ __forceinline__ void mma_tf32(float* c, const uint32_t* a, const uint32_t* b) {
    asm volatile(
        "mma.sync.aligned.m16n8k8.row.col.f32.tf32.tf32.f32 "
        "{%0,%1,%2,%3}, {%4,%5,%6,%7}, {%8,%9}, {%0,%1,%2,%3};"
        : "+f"(c[0]), "+f"(c[1]), "+f"(c[2]), "+f"(c[3])
        : "r"(a[0]), "r"(a[1]), "r"(a[2]), "r"(a[3]), "r"(b[0]), "r"(b[1]));
}

// ================= tf32 mma.sync GEMM: C[M,N] = A[M,K] * B[N,K]^T =================
// 128x128x32 CTA tile, 256 threads (8 warps, 2x4), warp tile 64x32 (4x4 m16n8k8),
// 2-stage cp.async pipeline, pad-36 smem rows (conflict-free fragment loads).
#define BK 32
#define PAD 36
#define ASZ (128 * PAD)            // floats per tile buffer
#define GEMM_SMEM (4 * ASZ * 4)    // 2 stages x (A+B) = 73728 bytes

__global__ __launch_bounds__(256, 2)
void gemm_tf32_mma(const float* __restrict__ A, const float* __restrict__ Bm,
                   float* __restrict__ C, int M, int N, int K)
{
    extern __shared__ __align__(16) float sm[];
    // layout: stage s: A at sm[s*ASZ], B at sm[2*ASZ + s*ASZ]
    uint32_t smem_base = smem_to_u32(sm);

    int tid  = threadIdx.x;
    int wid  = tid >> 5;
    int lane = tid & 31;
    int bm = blockIdx.y * 128;
    int bn = blockIdx.x * 128;

    int warpM = (wid >> 2) * 64;   // 0 or 64
    int warpN = (wid & 3) * 32;    // 0..96

    // loader mapping: 8 x 16B chunks per 32-float row; 32 rows per pass, 4 passes
    int lrow  = tid >> 3;          // 0..31
    int lcol  = (tid & 7) * 4;     // 0,4,...,28

    const int KT = K / BK;

    float acc[4][4][4];
#pragma unroll
    for (int i = 0; i < 4; i++)
#pragma unroll
        for (int j = 0; j < 4; j++)
#pragma unroll
            for (int q = 0; q < 4; q++) acc[i][j][q] = 0.f;

    auto load_stage = [&](int kt, int s) {
        const float* Ap = A + (size_t)(bm + lrow) * K + kt * BK + lcol;
        const float* Bp = Bm + (size_t)(bn + lrow) * K + kt * BK + lcol;
        uint32_t aBase = smem_base + (s * ASZ) * 4;
        uint32_t bBase = smem_base + (2 * ASZ + s * ASZ) * 4;
#pragma unroll
        for (int r = 0; r < 4; r++) {
            cp_async16(aBase + ((lrow + r * 32) * PAD + lcol) * 4,
                       Ap + (size_t)(r * 32) * K);
            cp_async16(bBase + ((lrow + r * 32) * PAD + lcol) * 4,
                       Bp + (size_t)(r * 32) * K);
        }
        CP_COMMIT();
    };

    load_stage(0, 0);

    for (int kt = 0; kt < KT; kt++) {
        int cur = kt & 1;
        if (kt + 1 < KT) {
            load_stage(kt + 1, cur ^ 1);
            CP_WAIT(1);
        } else {
            CP_WAIT(0);
        }
        __syncthreads();

        const float* As = sm + cur * ASZ;
        const float* Bs = sm + 2 * ASZ + cur * ASZ;
        int g = lane >> 2;         // group id 0..7
        int t = lane & 3;          // thread-in-group

#pragma unroll
        for (int kc = 0; kc < 4; kc++) {
            uint32_t bf[4][2];
#pragma unroll
            for (int nt = 0; nt < 4; nt++) {
                int n0 = warpN + nt * 8 + g;
                bf[nt][0] = f2tf32(Bs[n0 * PAD + kc * 8 + t]);
                bf[nt][1] = f2tf32(Bs[n0 * PAD + kc * 8 + t + 4]);
            }
#pragma unroll
            for (int mt = 0; mt < 4; mt++) {
                int r0 = warpM + mt * 16 + g;
                uint32_t af[4];
                af[0] = f2tf32(As[r0 * PAD + kc * 8 + t]);
                af[1] = f2tf32(As[(r0 + 8) * PAD + kc * 8 + t]);
                af[2] = f2tf32(As[r0 * PAD + kc * 8 + t + 4]);
                af[3] = f2tf32(As[(r0 + 8) * PAD + kc * 8 + t + 4]);
#pragma unroll
                for (int nt = 0; nt < 4; nt++)
                    mma_tf32(acc[mt][nt], af, bf[nt]);
            }
        }
        __syncthreads();
    }

    // epilogue: c0,c1 at (row, col..col+1), c2,c3 at (row+8, ...)
    {
        int g = lane >> 2;
        int t = lane & 3;
#pragma unroll
        for (int mt = 0; mt < 4; mt++) {
            int row = bm + warpM + mt * 16 + g;
#pragma unroll
            for (int nt = 0; nt < 4; nt++) {
                int col = bn + warpN + nt * 8 + t * 2;
                float2 v0 = make_float2(acc[mt][nt][0], acc[mt][nt][1]);
                float2 v1 = make_float2(acc[mt][nt][2], acc[mt][nt][3]);
                *(float2*)(C + (size_t)row * N + col)       = v0;
                *(float2*)(C + (size_t)(row + 8) * N + col) = v1;
            }
        }
    }
}

// ---------------- 1) residual causal depthwise conv ----------------
__global__ __launch_bounds__(256) void conv_residual(
    const float* __restrict__ x, const float* __restrict__ w,
    const float* __restrict__ cb)
{
    int idx = blockIdx.x * blockDim.x + threadIdx.x;
    int h4 = idx & 255;
    int t  = (idx >> 8) & (Tt - 1);
    int b  = idx >> (8 + 13);
    size_t base = (((size_t)b * Tt + t) * Hh) + (size_t)h4 * 4;

    float4 xc = *(const float4*)(x + base);
    float4 bc = *(const float4*)(cb + (size_t)h4 * 4);
    float4 acc;
    acc.x = xc.x + bc.x; acc.y = xc.y + bc.y;
    acc.z = xc.z + bc.z; acc.w = xc.w + bc.w;

#pragma unroll
    for (int i = 0; i < 4; i++) {
        int ts = t - 3 + i;
        if (ts >= 0) {
            float4 xi = (i == 3) ? xc
                : *(const float4*)(x + base + (long long)(i - 3) * Hh);
            float4 wi = *(const float4*)(w + (size_t)i * Hh + (size_t)h4 * 4);
            acc.x += wi.x * xi.x; acc.y += wi.y * xi.y;
            acc.z += wi.z * xi.z; acc.w += wi.w * xi.w;
        }
    }
    *(float4*)(g_x1 + base) = acc;
}

// ---------------- 3) scan: sigmoid + linear recurrence ----------------
__device__ __forceinline__ void gru_ab(float z, float hc, float& a, float& bb)
{
    float s = 1.f / (1.f + __expf(-z));
    a = 1.f - s;
    bb = s * hc;
}

__global__ __launch_bounds__(128) void scan_passA()
{
    int r   = blockIdx.x * 128 + threadIdx.x;
    int seg = blockIdx.y;
    int b   = blockIdx.z;
    size_t base = (size_t)b * Tt * N1;
    float A = 1.f, Cc = 0.f;
    int t0 = seg * SEGLEN;
    for (int t = t0; t < t0 + SEGLEN; t++) {
        size_t off = base + (size_t)t * N1;
        float z  = g_zh[off + r];
        float hc = g_zh[off + Rr + r];
        float a, bb; gru_ab(z, hc, a, bb);
        A  *= a;
        Cc = a * Cc + bb;
    }
    size_t i = ((size_t)b * NSEG + seg) * Rr + r;
    g_segA[i] = A;
    g_segC[i] = Cc;
}

__global__ __launch_bounds__(128) void scan_passB()
{
    int r = blockIdx.x * 128 + threadIdx.x;
    int b = blockIdx.z;
    float h = 0.f;
    for (int seg = 0; seg < NSEG; seg++) {
        size_t i = ((size_t)b * NSEG + seg) * Rr + r;
        g_hin[i] = h;
        h = g_segA[i] * h + g_segC[i];
    }
}

__global__ __launch_bounds__(128) void scan_passC()
{
    int r   = blockIdx.x * 128 + threadIdx.x;
    int seg = blockIdx.y;
    int b   = blockIdx.z;
    size_t base = (size_t)b * Tt * N1;
    float h = g_hin[((size_t)b * NSEG + seg) * Rr + r];
    int t0 = seg * SEGLEN;
    for (int t = t0; t < t0 + SEGLEN; t++) {
        size_t off = base + (size_t)t * N1;
        float z  = g_zh[off + r];
        float hc = g_zh[off + Rr + r];
        float a, bb; gru_ab(z, hc, a, bb);
        h = a * h + bb;
        g_ho[((size_t)b * Tt + t) * Rr + r] = h;
    }
}

// ---------------- launch ----------------
extern "C" void kernel_launch(void* const* d_in, const int* in_sizes, int n_in,
                              void* d_out, int out_size)
{
    const float* x      = (const float*)d_in[0];
    const float* w_zh   = (const float*)d_in[1];
    const float* w_out  = (const float*)d_in[2];
    const float* conv_w = (const float*)d_in[3];
    const float* conv_b = (const float*)d_in[4];
    float* out = (float*)d_out;

    float* x1 = nullptr; float* zh = nullptr; float* ho = nullptr;
    cudaGetSymbolAddress((void**)&x1, g_x1);
    cudaGetSymbolAddress((void**)&zh, g_zh);
    cudaGetSymbolAddress((void**)&ho, g_ho);

    cudaFuncSetAttribute(gemm_tf32_mma,
                         cudaFuncAttributeMaxDynamicSharedMemorySize, GEMM_SMEM);

    // 1) conv
    {
        int total4 = Bb * Tt * (Hh / 4);
        conv_residual<<<total4 / 256, 256>>>(x, conv_w, conv_b);
    }
    // 2) GEMM1: zh[BT, 2R] = x1[BT, H] * w_zh[2R, H]^T
    {
        dim3 grid(N1 / 128, (Bb * Tt) / 128);
        gemm_tf32_mma<<<grid, 256, GEMM_SMEM>>>(x1, w_zh, zh, Bb * Tt, N1, Hh);
    }
    // 3) scan
    {
        dim3 gA(Rr / 128, NSEG, Bb);
        scan_passA<<<gA, 128>>>();
        dim3 gB(Rr / 128, 1, Bb);
        scan_passB<<<gB, 128>>>();
        scan_passC<<<gA, 128>>>();
    }
    // 4) GEMM2: out[BT, H] = ho[BT, R] * w_out[H, R]^T
    {
        dim3 grid(Hh / 128, (Bb * Tt) / 128);
        gemm_tf32_mma<<<grid, 256, GEMM_SMEM>>>(ho, w_out, out, Bb * Tt, Hh, Rr);
    }
}

// round 4
// speedup vs baseline: 3.5585x; 1.1700x over previous
#include <cuda_runtime.h>
#include <cstdint>

// Problem constants
#define Bb 4
#define Tt 8192
#define Hh 1024
#define Rr 1024
#define N1 2048          // 2*R
#define NSEG 64
#define SEGLEN 128       // Tt / NSEG

// ---------------- scratch (static device globals; no allocation) ----------------
__device__ float g_x1[(size_t)Bb * Tt * Hh];        // conv output, tf32-rounded
__device__ float g_zh[(size_t)Bb * Tt * N1];        // GEMM1 output
__device__ float g_ho[(size_t)Bb * Tt * Rr];        // scan output, tf32-rounded
__device__ float g_segA[(size_t)Bb * NSEG * Rr];
__device__ float g_segC[(size_t)Bb * NSEG * Rr];
__device__ float g_hin [(size_t)Bb * NSEG * Rr];
__device__ float g_wzhT [(size_t)N1 * Hh];          // w_zh  tf32 + k-interleaved
__device__ float g_woutT[(size_t)Hh * Rr];          // w_out tf32 + k-interleaved

// ================= helpers =================
__device__ __forceinline__ uint32_t smem_to_u32(const void* p) {
    uint32_t a;
    asm("{ .reg .u64 t; cvta.to.shared.u64 t, %1; cvt.u32.u64 %0, t; }" : "=r"(a) : "l"(p));
    return a;
}
__device__ __forceinline__ void cp_async16(uint32_t dst, const void* src) {
    asm volatile("cp.async.cg.shared.global [%0], [%1], 16;" :: "r"(dst), "l"(src) : "memory");
}
#define CP_COMMIT() asm volatile("cp.async.commit_group;" ::: "memory")
#define CP_WAIT(n)  asm volatile("cp.async.wait_group %0;" :: "n"(n) : "memory")

__device__ __forceinline__ uint32_t f2tf32(float f) {
    uint32_t r;
    asm("cvt.rna.tf32.f32 %0, %1;" : "=r"(r) : "f"(f));
    return r;
}
__device__ __forceinline__ float round_tf32(float f) {
    return __uint_as_float(f2tf32(f));
}
__device__ __forceinline__ void mma_tf32(float* c, const uint32_t* a, const uint32_t* b) {
    asm volatile(
        "mma.sync.aligned.m16n8k8.row.col.f32.tf32.tf32.f32 "
        "{%0,%1,%2,%3}, {%4,%5,%6,%7}, {%8,%9}, {%0,%1,%2,%3};"
        : "+f"(c[0]), "+f"(c[1]), "+f"(c[2]), "+f"(c[3])
        : "r"(a[0]), "r"(a[1]), "r"(a[2]), "r"(a[3]), "r"(b[0]), "r"(b[1]));
}
__device__ __forceinline__ void ldmatrix_x4(uint32_t* r, uint32_t addr) {
    asm volatile("ldmatrix.sync.aligned.m8n8.x4.shared.b16 {%0,%1,%2,%3}, [%4];"
        : "=r"(r[0]), "=r"(r[1]), "=r"(r[2]), "=r"(r[3]) : "r"(addr));
}

// ================= weight prep: tf32 round + k-interleave =================
// dst[n][8g + q] = tf32( src[n][8g + (q>>1) + (q&1)*4] )
// so pair (b0,b1) = cols (t, t+4) lands at adjacent words 2t, 2t+1.
__global__ __launch_bounds__(256) void prep_weight(
    const float* __restrict__ src, float* __restrict__ dst, int total)
{
    int idx = blockIdx.x * blockDim.x + threadIdx.x;
    if (idx >= total) return;
    int q = idx & 7;
    int base = idx & ~7;
    int orig = base + (q >> 1) + (q & 1) * 4;
    dst[idx] = round_tf32(src[orig]);
}

// ================= tf32 mma.sync GEMM: C[M,N] = A[M,K] * B[N,K]^T =================
// A: natural row-major (tf32 pre-rounded). B: k-interleaved (prep_weight).
// 128x128x32 CTA tile, 8 warps, warp 64x32, ldmatrix A frags, LDS.64 B frags.
#define BK 32
#define PADA 36
#define PADB 40
#define ASTG (128 * PADA)          // words per A stage
#define BSTG (128 * PADB)          // words per B stage
#define GEMM_SMEM ((2 * ASTG + 2 * BSTG) * 4)   // 77824 bytes

__global__ __launch_bounds__(256, 2)
void gemm_tf32_mma(const float* __restrict__ A, const float* __restrict__ Bm,
                   float* __restrict__ C, int M, int N, int K)
{
    extern __shared__ __align__(16) float sm[];
    uint32_t smem_base = smem_to_u32(sm);

    int tid  = threadIdx.x;
    int wid  = tid >> 5;
    int lane = tid & 31;
    int bm = blockIdx.y * 128;
    int bn = blockIdx.x * 128;

    int warpM = (wid >> 2) * 64;   // 0 or 64
    int warpN = (wid & 3) * 32;    // 0..96

    int lrow  = tid >> 3;          // 0..31
    int lcol  = (tid & 7) * 4;     // 0,4,...,28

    // ldmatrix lane address components
    int row_off = ((lane >> 3) & 1) * 8 + (lane & 7);
    int col_off = (lane >> 4) * 4;
    int g = lane >> 2;
    int t = lane & 3;

    const int KT = K / BK;

    float acc[4][4][4];
#pragma unroll
    for (int i = 0; i < 4; i++)
#pragma unroll
        for (int j = 0; j < 4; j++)
#pragma unroll
            for (int q = 0; q < 4; q++) acc[i][j][q] = 0.f;

    auto load_stage = [&](int kt, int s) {
        const float* Ap = A + (size_t)(bm + lrow) * K + kt * BK + lcol;
        const float* Bp = Bm + (size_t)(bn + lrow) * K + kt * BK + lcol;
        uint32_t aB = smem_base + (s * ASTG) * 4;
        uint32_t bB = smem_base + (2 * ASTG + s * BSTG) * 4;
#pragma unroll
        for (int r = 0; r < 4; r++) {
            cp_async16(aB + ((lrow + r * 32) * PADA + lcol) * 4,
                       Ap + (size_t)(r * 32) * K);
            cp_async16(bB + ((lrow + r * 32) * PADB + lcol) * 4,
                       Bp + (size_t)(r * 32) * K);
        }
        CP_COMMIT();
    };

    load_stage(0, 0);

    for (int kt = 0; kt < KT; kt++) {
        int cur = kt & 1;
        if (kt + 1 < KT) {
            load_stage(kt + 1, cur ^ 1);
            CP_WAIT(1);
        } else {
            CP_WAIT(0);
        }
        __syncthreads();

        const float* Bs = sm + 2 * ASTG + cur * BSTG;
        uint32_t aAddr = smem_base + (cur * ASTG) * 4
                       + ((warpM + row_off) * PADA + col_off) * 4;

#pragma unroll
        for (int kc = 0; kc < 4; kc++) {
            uint2 bfr[4];
#pragma unroll
            for (int nt = 0; nt < 4; nt++) {
                bfr[nt] = *(const uint2*)(Bs + (warpN + nt * 8 + g) * PADB
                                             + kc * 8 + 2 * t);
            }
            uint32_t afr[4][4];
#pragma unroll
            for (int mt = 0; mt < 4; mt++) {
                ldmatrix_x4(afr[mt], aAddr + (mt * 16 * PADA + kc * 8) * 4);
            }
#pragma unroll
            for (int mt = 0; mt < 4; mt++)
#pragma unroll
                for (int nt = 0; nt < 4; nt++)
                    mma_tf32(acc[mt][nt], afr[mt], (const uint32_t*)&bfr[nt]);
        }
        __syncthreads();
    }

    // epilogue
    {
#pragma unroll
        for (int mt = 0; mt < 4; mt++) {
            int row = bm + warpM + mt * 16 + g;
#pragma unroll
            for (int nt = 0; nt < 4; nt++) {
                int col = bn + warpN + nt * 8 + t * 2;
                float2 v0 = make_float2(acc[mt][nt][0], acc[mt][nt][1]);
                float2 v1 = make_float2(acc[mt][nt][2], acc[mt][nt][3]);
                *(float2*)(C + (size_t)row * N + col)       = v0;
                *(float2*)(C + (size_t)(row + 8) * N + col) = v1;
            }
        }
    }
}

// ---------------- 1) residual causal depthwise conv (tf32-rounded out) ----------------
__global__ __launch_bounds__(256) void conv_residual(
    const float* __restrict__ x, const float* __restrict__ w,
    const float* __restrict__ cb)
{
    int idx = blockIdx.x * blockDim.x + threadIdx.x;
    int h4 = idx & 255;
    int t  = (idx >> 8) & (Tt - 1);
    int b  = idx >> (8 + 13);
    size_t base = (((size_t)b * Tt + t) * Hh) + (size_t)h4 * 4;

    float4 xc = *(const float4*)(x + base);
    float4 bc = *(const float4*)(cb + (size_t)h4 * 4);
    float4 acc;
    acc.x = xc.x + bc.x; acc.y = xc.y + bc.y;
    acc.z = xc.z + bc.z; acc.w = xc.w + bc.w;

#pragma unroll
    for (int i = 0; i < 4; i++) {
        int ts = t - 3 + i;
        if (ts >= 0) {
            float4 xi = (i == 3) ? xc
                : *(const float4*)(x + base + (long long)(i - 3) * Hh);
            float4 wi = *(const float4*)(w + (size_t)i * Hh + (size_t)h4 * 4);
            acc.x += wi.x * xi.x; acc.y += wi.y * xi.y;
            acc.z += wi.z * xi.z; acc.w += wi.w * xi.w;
        }
    }
    acc.x = round_tf32(acc.x); acc.y = round_tf32(acc.y);
    acc.z = round_tf32(acc.z); acc.w = round_tf32(acc.w);
    *(float4*)(g_x1 + base) = acc;
}

// ---------------- 3) scan: sigmoid + linear recurrence ----------------
__device__ __forceinline__ void gru_ab(float z, float hc, float& a, float& bb)
{
    float s = 1.f / (1.f + __expf(-z));
    a = 1.f - s;
    bb = s * hc;
}

__global__ __launch_bounds__(128) void scan_passA()
{
    int r   = blockIdx.x * 128 + threadIdx.x;
    int seg = blockIdx.y;
    int b   = blockIdx.z;
    size_t base = (size_t)b * Tt * N1;
    float A = 1.f, Cc = 0.f;
    int t0 = seg * SEGLEN;
    for (int t = t0; t < t0 + SEGLEN; t++) {
        size_t off = base + (size_t)t * N1;
        float z  = g_zh[off + r];
        float hc = g_zh[off + Rr + r];
        float a, bb; gru_ab(z, hc, a, bb);
        A  *= a;
        Cc = a * Cc + bb;
    }
    size_t i = ((size_t)b * NSEG + seg) * Rr + r;
    g_segA[i] = A;
    g_segC[i] = Cc;
}

__global__ __launch_bounds__(128) void scan_passB()
{
    int r = blockIdx.x * 128 + threadIdx.x;
    int b = blockIdx.z;
    float h = 0.f;
    for (int seg = 0; seg < NSEG; seg++) {
        size_t i = ((size_t)b * NSEG + seg) * Rr + r;
        g_hin[i] = h;
        h = g_segA[i] * h + g_segC[i];
    }
}

__global__ __launch_bounds__(128) void scan_passC()
{
    int r   = blockIdx.x * 128 + threadIdx.x;
    int seg = blockIdx.y;
    int b   = blockIdx.z;
    size_t base = (size_t)b * Tt * N1;
    float h = g_hin[((size_t)b * NSEG + seg) * Rr + r];
    int t0 = seg * SEGLEN;
    for (int t = t0; t < t0 + SEGLEN; t++) {
        size_t off = base + (size_t)t * N1;
        float z  = g_zh[off + r];
        float hc = g_zh[off + Rr + r];
        float a, bb; gru_ab(z, hc, a, bb);
        h = a * h + bb;
        g_ho[((size_t)b * Tt + t) * Rr + r] = round_tf32(h);
    }
}

// ---------------- launch ----------------
extern "C" void kernel_launch(void* const* d_in, const int* in_sizes, int n_in,
                              void* d_out, int out_size)
{
    const float* x      = (const float*)d_in[0];
    const float* w_zh   = (const float*)d_in[1];
    const float* w_out  = (const float*)d_in[2];
    const float* conv_w = (const float*)d_in[3];
    const float* conv_b = (const float*)d_in[4];
    float* out = (float*)d_out;

    float* x1 = nullptr; float* zh = nullptr; float* ho = nullptr;
    float* wzhT = nullptr; float* woutT = nullptr;
    cudaGetSymbolAddress((void**)&x1, g_x1);
    cudaGetSymbolAddress((void**)&zh, g_zh);
    cudaGetSymbolAddress((void**)&ho, g_ho);
    cudaGetSymbolAddress((void**)&wzhT, g_wzhT);
    cudaGetSymbolAddress((void**)&woutT, g_woutT);

    cudaFuncSetAttribute(gemm_tf32_mma,
                         cudaFuncAttributeMaxDynamicSharedMemorySize, GEMM_SMEM);

    // 0) weight prep (tf32 round + interleave)
    {
        int tw1 = N1 * Hh;
        prep_weight<<<(tw1 + 255) / 256, 256>>>(w_zh, wzhT, tw1);
        int tw2 = Hh * Rr;
        prep_weight<<<(tw2 + 255) / 256, 256>>>(w_out, woutT, tw2);
    }
    // 1) conv
    {
        int total4 = Bb * Tt * (Hh / 4);
        conv_residual<<<total4 / 256, 256>>>(x, conv_w, conv_b);
    }
    // 2) GEMM1: zh[BT, 2R] = x1[BT, H] * w_zh[2R, H]^T
    {
        dim3 grid(N1 / 128, (Bb * Tt) / 128);
        gemm_tf32_mma<<<grid, 256, GEMM_SMEM>>>(x1, wzhT, zh, Bb * Tt, N1, Hh);
    }
    // 3) scan
    {
        dim3 gA(Rr / 128, NSEG, Bb);
        scan_passA<<<gA, 128>>>();
        dim3 gB(Rr / 128, 1, Bb);
        scan_passB<<<gB, 128>>>();
        scan_passC<<<gA, 128>>>();
    }
    // 4) GEMM2: out[BT, H] = ho[BT, R] * w_out[H, R]^T
    {
        dim3 grid(Hh / 128, (Bb * Tt) / 128);
        gemm_tf32_mma<<<grid, 256, GEMM_SMEM>>>(ho, woutT, out, Bb * Tt, Hh, Rr);
    }
}

// round 5
// speedup vs baseline: 3.6023x; 1.0123x over previous
#include <cuda_runtime.h>
#include <cstdint>

// Problem constants
#define Bb 4
#define Tt 8192
#define Hh 1024
#define Rr 1024
#define N1 2048          // 2*R
#define NSEG 64
#define SEGLEN 128       // Tt / NSEG

// ---------------- scratch (static device globals; no allocation) ----------------
__device__ float g_x1[(size_t)Bb * Tt * Hh];        // conv output, tf32-rounded
__device__ float g_zh[(size_t)Bb * Tt * N1];        // GEMM1 output
__device__ float g_ho[(size_t)Bb * Tt * Rr];        // scan output, tf32-rounded
__device__ float g_segA[(size_t)Bb * NSEG * Rr];
__device__ float g_segC[(size_t)Bb * NSEG * Rr];
__device__ float g_hin [(size_t)Bb * NSEG * Rr];
__device__ float g_wzhT [(size_t)N1 * Hh];          // w_zh  tf32-rounded
__device__ float g_woutT[(size_t)Hh * Rr];          // w_out tf32-rounded

// ================= helpers =================
__device__ __forceinline__ uint32_t smem_to_u32(const void* p) {
    uint32_t a;
    asm("{ .reg .u64 t; cvta.to.shared.u64 t, %1; cvt.u32.u64 %0, t; }" : "=r"(a) : "l"(p));
    return a;
}
__device__ __forceinline__ void cp_async16(uint32_t dst, const void* src) {
    asm volatile("cp.async.cg.shared.global [%0], [%1], 16;" :: "r"(dst), "l"(src) : "memory");
}
#define CP_COMMIT() asm volatile("cp.async.commit_group;" ::: "memory")
#define CP_WAIT(n)  asm volatile("cp.async.wait_group %0;" :: "n"(n) : "memory")

__device__ __forceinline__ uint32_t f2tf32(float f) {
    uint32_t r;
    asm("cvt.rna.tf32.f32 %0, %1;" : "=r"(r) : "f"(f));
    return r;
}
__device__ __forceinline__ float round_tf32(float f) {
    return __uint_as_float(f2tf32(f));
}
__device__ __forceinline__ void mma_tf32(float* c, const uint32_t* a, const uint32_t* b) {
    asm volatile(
        "mma.sync.aligned.m16n8k8.row.col.f32.tf32.tf32.f32 "
        "{%0,%1,%2,%3}, {%4,%5,%6,%7}, {%8,%9}, {%0,%1,%2,%3};"
        : "+f"(c[0]), "+f"(c[1]), "+f"(c[2]), "+f"(c[3])
        : "r"(a[0]), "r"(a[1]), "r"(a[2]), "r"(a[3]), "r"(b[0]), "r"(b[1]));
}
__device__ __forceinline__ void ldmatrix_x4(uint32_t* r, uint32_t addr) {
    asm volatile("ldmatrix.sync.aligned.m8n8.x4.shared.b16 {%0,%1,%2,%3}, [%4];"
        : "=r"(r[0]), "=r"(r[1]), "=r"(r[2]), "=r"(r[3]) : "r"(addr));
}

// ================= weight prep: tf32 round =================
__global__ __launch_bounds__(256) void prep_weight(
    const float* __restrict__ src, float* __restrict__ dst, int total)
{
    int idx = blockIdx.x * blockDim.x + threadIdx.x;
    if (idx >= total) return;
    dst[idx] = round_tf32(src[idx]);
}

// ================= tf32 mma.sync GEMM: C[M,N] = A[M,K] * B[N,K]^T =================
// 128x128x16 CTA tile, 8 warps (2x4), warp tile 64x32, 4-stage cp.async ring,
// ldmatrix.x4 for both A and B fragments, pitch-20 smem rows (conflict-free).
#define BK 16
#define PITCH 20
#define ASTG (128 * PITCH)         // words per A stage (= B stage)
#define NST 4
#define GEMM_SMEM (NST * 2 * ASTG * 4)   // 81920 bytes

__global__ __launch_bounds__(256, 2)
void gemm_tf32_mma(const float* __restrict__ A, const float* __restrict__ Bm,
                   float* __restrict__ C, int M, int N, int K)
{
    extern __shared__ __align__(16) float sm[];
    uint32_t smem_base = smem_to_u32(sm);

    int tid  = threadIdx.x;
    int wid  = tid >> 5;
    int lane = tid & 31;
    int bm = blockIdx.y * 128;
    int bn = blockIdx.x * 128;

    int warpM = (wid >> 2) * 64;   // 0 or 64
    int warpN = (wid & 3) * 32;    // 0..96

    // A ldmatrix lane addressing (16x8 f32 tile = 4 b16 8x8 matrices)
    int a_row = ((lane >> 3) & 1) * 8 + (lane & 7);
    int a_col = (lane >> 4) * 4;
    // B ldmatrix lane addressing (two 8x8 f32 tiles stacked = 4 b16 matrices)
    int b_row = (lane >> 4) * 8 + (lane & 7);
    int b_byte = ((lane >> 3) & 1) * 16;

    int g = lane >> 2;
    int t = lane & 3;

    const int KT = K / BK;

    float acc[4][4][4];
#pragma unroll
    for (int i = 0; i < 4; i++)
#pragma unroll
        for (int j = 0; j < 4; j++)
#pragma unroll
            for (int q = 0; q < 4; q++) acc[i][j][q] = 0.f;

    auto load_stage = [&](int kt, int s) {
        uint32_t aB = smem_base + (s * 2 * ASTG) * 4;
        uint32_t bB = aB + ASTG * 4;
#pragma unroll
        for (int r = 0; r < 2; r++) {
            int c   = tid + 256 * r;       // 0..511
            int row = c >> 2;
            int col = (c & 3) * 4;
            cp_async16(aB + (row * PITCH + col) * 4,
                       A + (size_t)(bm + row) * K + kt * BK + col);
            cp_async16(bB + (row * PITCH + col) * 4,
                       Bm + (size_t)(bn + row) * K + kt * BK + col);
        }
        CP_COMMIT();
    };

    // prologue: 3 stages in flight
    load_stage(0, 0);
    load_stage(1, 1);
    load_stage(2, 2);

    for (int kt = 0; kt < KT; kt++) {
        CP_WAIT(2);
        __syncthreads();

        int s = kt & (NST - 1);
        uint32_t aBase = smem_base + (s * 2 * ASTG) * 4
                       + ((warpM + a_row) * PITCH + a_col) * 4;
        uint32_t bBase = smem_base + (s * 2 * ASTG + ASTG) * 4
                       + ((warpN + b_row) * PITCH) * 4 + b_byte;

#pragma unroll
        for (int kc = 0; kc < 2; kc++) {
            uint32_t bfr[4][2];
#pragma unroll
            for (int nt2 = 0; nt2 < 2; nt2++) {
                uint32_t r[4];
                ldmatrix_x4(r, bBase + (nt2 * 16 * PITCH + kc * 8) * 4);
                bfr[2 * nt2][0]     = r[0];
                bfr[2 * nt2][1]     = r[1];
                bfr[2 * nt2 + 1][0] = r[2];
                bfr[2 * nt2 + 1][1] = r[3];
            }
#pragma unroll
            for (int mt = 0; mt < 4; mt++) {
                uint32_t afr[4];
                ldmatrix_x4(afr, aBase + (mt * 16 * PITCH + kc * 8) * 4);
#pragma unroll
                for (int nt = 0; nt < 4; nt++)
                    mma_tf32(acc[mt][nt], afr, bfr[nt]);
            }
        }

        if (kt + 3 < KT) load_stage(kt + 3, (kt + 3) & (NST - 1));
        else             CP_COMMIT();      // keep group count in lockstep
    }

    // epilogue
    {
#pragma unroll
        for (int mt = 0; mt < 4; mt++) {
            int row = bm + warpM + mt * 16 + g;
#pragma unroll
            for (int nt = 0; nt < 4; nt++) {
                int col = bn + warpN + nt * 8 + t * 2;
                float2 v0 = make_float2(acc[mt][nt][0], acc[mt][nt][1]);
                float2 v1 = make_float2(acc[mt][nt][2], acc[mt][nt][3]);
                *(float2*)(C + (size_t)row * N + col)       = v0;
                *(float2*)(C + (size_t)(row + 8) * N + col) = v1;
            }
        }
    }
}

// ---------------- 1) residual causal depthwise conv (tf32-rounded out) ----------------
__global__ __launch_bounds__(256) void conv_residual(
    const float* __restrict__ x, const float* __restrict__ w,
    const float* __restrict__ cb)
{
    int idx = blockIdx.x * blockDim.x + threadIdx.x;
    int h4 = idx & 255;
    int t  = (idx >> 8) & (Tt - 1);
    int b  = idx >> (8 + 13);
    size_t base = (((size_t)b * Tt + t) * Hh) + (size_t)h4 * 4;

    float4 xc = *(const float4*)(x + base);
    float4 bc = *(const float4*)(cb + (size_t)h4 * 4);
    float4 acc;
    acc.x = xc.x + bc.x; acc.y = xc.y + bc.y;
    acc.z = xc.z + bc.z; acc.w = xc.w + bc.w;

#pragma unroll
    for (int i = 0; i < 4; i++) {
        int ts = t - 3 + i;
        if (ts >= 0) {
            float4 xi = (i == 3) ? xc
                : *(const float4*)(x + base + (long long)(i - 3) * Hh);
            float4 wi = *(const float4*)(w + (size_t)i * Hh + (size_t)h4 * 4);
            acc.x += wi.x * xi.x; acc.y += wi.y * xi.y;
            acc.z += wi.z * xi.z; acc.w += wi.w * xi.w;
        }
    }
    acc.x = round_tf32(acc.x); acc.y = round_tf32(acc.y);
    acc.z = round_tf32(acc.z); acc.w = round_tf32(acc.w);
    *(float4*)(g_x1 + base) = acc;
}

// ---------------- 3) scan: sigmoid + linear recurrence ----------------
__device__ __forceinline__ void gru_ab(float z, float hc, float& a, float& bb)
{
    float s = 1.f / (1.f + __expf(-z));
    a = 1.f - s;
    bb = s * hc;
}

__global__ __launch_bounds__(128) void scan_passA()
{
    int r   = blockIdx.x * 128 + threadIdx.x;
    int seg = blockIdx.y;
    int b   = blockIdx.z;
    size_t base = (size_t)b * Tt * N1;
    float A = 1.f, Cc = 0.f;
    int t0 = seg * SEGLEN;
    for (int t = t0; t < t0 + SEGLEN; t++) {
        size_t off = base + (size_t)t * N1;
        float z  = g_zh[off + r];
        float hc = g_zh[off + Rr + r];
        float a, bb; gru_ab(z, hc, a, bb);
        A  *= a;
        Cc = a * Cc + bb;
    }
    size_t i = ((size_t)b * NSEG + seg) * Rr + r;
    g_segA[i] = A;
    g_segC[i] = Cc;
}

__global__ __launch_bounds__(128) void scan_passB()
{
    int r = blockIdx.x * 128 + threadIdx.x;
    int b = blockIdx.z;
    float h = 0.f;
    for (int seg = 0; seg < NSEG; seg++) {
        size_t i = ((size_t)b * NSEG + seg) * Rr + r;
        g_hin[i] = h;
        h = g_segA[i] * h + g_segC[i];
    }
}

__global__ __launch_bounds__(128) void scan_passC()
{
    int r   = blockIdx.x * 128 + threadIdx.x;
    int seg = blockIdx.y;
    int b   = blockIdx.z;
    size_t base = (size_t)b * Tt * N1;
    float h = g_hin[((size_t)b * NSEG + seg) * Rr + r];
    int t0 = seg * SEGLEN;
    for (int t = t0; t < t0 + SEGLEN; t++) {
        size_t off = base + (size_t)t * N1;
        float z  = g_zh[off + r];
        float hc = g_zh[off + Rr + r];
        float a, bb; gru_ab(z, hc, a, bb);
        h = a * h + bb;
        g_ho[((size_t)b * Tt + t) * Rr + r] = round_tf32(h);
    }
}

// ---------------- launch ----------------
extern "C" void kernel_launch(void* const* d_in, const int* in_sizes, int n_in,
                              void* d_out, int out_size)
{
    const float* x      = (const float*)d_in[0];
    const float* w_zh   = (const float*)d_in[1];
    const float* w_out  = (const float*)d_in[2];
    const float* conv_w = (const float*)d_in[3];
    const float* conv_b = (const float*)d_in[4];
    float* out = (float*)d_out;

    float* x1 = nullptr; float* zh = nullptr; float* ho = nullptr;
    float* wzhT = nullptr; float* woutT = nullptr;
    cudaGetSymbolAddress((void**)&x1, g_x1);
    cudaGetSymbolAddress((void**)&zh, g_zh);
    cudaGetSymbolAddress((void**)&ho, g_ho);
    cudaGetSymbolAddress((void**)&wzhT, g_wzhT);
    cudaGetSymbolAddress((void**)&woutT, g_woutT);

    cudaFuncSetAttribute(gemm_tf32_mma,
                         cudaFuncAttributeMaxDynamicSharedMemorySize, GEMM_SMEM);

    // 0) weight prep (tf32 round)
    {
        int tw1 = N1 * Hh;
        prep_weight<<<(tw1 + 255) / 256, 256>>>(w_zh, wzhT, tw1);
        int tw2 = Hh * Rr;
        prep_weight<<<(tw2 + 255) / 256, 256>>>(w_out, woutT, tw2);
    }
    // 1) conv
    {
        int total4 = Bb * Tt * (Hh / 4);
        conv_residual<<<total4 / 256, 256>>>(x, conv_w, conv_b);
    }
    // 2) GEMM1: zh[BT, 2R] = x1[BT, H] * w_zh[2R, H]^T
    {
        dim3 grid(N1 / 128, (Bb * Tt) / 128);
        gemm_tf32_mma<<<grid, 256, GEMM_SMEM>>>(x1, wzhT, zh, Bb * Tt, N1, Hh);
    }
    // 3) scan
    {
        dim3 gA(Rr / 128, NSEG, Bb);
        scan_passA<<<gA, 128>>>();
        dim3 gB(Rr / 128, 1, Bb);
        scan_passB<<<gB, 128>>>();
        scan_passC<<<gA, 128>>>();
    }
    // 4) GEMM2: out[BT, H] = ho[BT, R] * w_out[H, R]^T
    {
        dim3 grid(Hh / 128, (Bb * Tt) / 128);
        gemm_tf32_mma<<<grid, 256, GEMM_SMEM>>>(ho, woutT, out, Bb * Tt, Hh, Rr);
    }
}